// round 11
// baseline (speedup 1.0000x reference)
#include <cuda_runtime.h>

// img:  (1, 64, 64, 1024) float32
// rois: (1, 1024, 4) int32  -> x, y, w, h
// out:  (1, 1024, 7, 7, 1024) float32
//
// One CTA per (roi, py); 256 threads, one float4 channel lane each.
// Explicit software pipeline: 3 register slots, prefetch distance 2.
// Iteration px computes from slot px%3 while loads for px+2 are in flight,
// keeping ~8-12 independent LDG.128 outstanding per thread (L1 is the
// binding pipe; deeper MLP > occupancy on this kernel, measured R6 vs R7).

#define POOL 7
#define HW 64
#define CV 256   // float4 lanes per pixel

__global__ __launch_bounds__(256, 3) void roi_pool_kernel(
    const float* __restrict__ img_,
    const int* __restrict__ rois,
    float* __restrict__ out_)
{
    const float4* __restrict__ img = reinterpret_cast<const float4*>(img_);
    float4* __restrict__ out = reinterpret_cast<float4*>(out_);

    const int py  = blockIdx.x;   // 0..6
    const int roi = blockIdx.y;   // 0..1023

    const int4 r = reinterpret_cast<const int4*>(rois)[roi];
    const int rx = r.x, ry = r.y, rw = r.z, rh = r.w;

    // ---- y axis (once per block) ----
    const float sy   = (float)rh / (float)POOL;
    const float srcy = ((float)py + 0.5f) * sy - 0.5f;
    const float fy   = floorf(srcy);
    const float ty   = srcy - fy;
    const int ylo = min(max((int)fy,     0), rh - 1);
    const int yhi = min(max((int)fy + 1, 0), rh - 1);

    const float4* __restrict__ rowT = img + (size_t)((ry + ylo) * HW) * CV;
    const float4* __restrict__ rowB = img + (size_t)((ry + yhi) * HW) * CV;

    const int c = threadIdx.x;
    float4* __restrict__ o = out + ((size_t)roi * (POOL * POOL) + (size_t)py * POOL) * CV + c;

    const float sx   = (float)rw / (float)POOL;
    const float wty  = ty;
    const float wmty = 1.0f - ty;

    // ---- x coords / weights (block-uniform, precomputed) ----
    int xA[POOL], xB[POOL];
    float wx[POOL];
    #pragma unroll
    for (int px = 0; px < POOL; px++) {
        const float srcx = ((float)px + 0.5f) * sx - 0.5f;
        const float fx   = floorf(srcx);
        wx[px] = srcx - fx;
        const int xlo = min(max((int)fx,     0), rw - 1);
        const int xhi = min(max((int)fx + 1, 0), rw - 1);
        xA[px] = rx + xlo;
        xB[px] = rx + xhi;
    }

    // ---- 3-slot software pipeline, prefetch distance 2 ----
    float4 Ta[3], Tb[3], Ba[3], Bb[3];

    // prime slots 0 and 1
    #pragma unroll
    for (int p = 0; p < 2; p++) {
        Ta[p] = __ldg(rowT + (size_t)xA[p] * CV + c);
        Tb[p] = __ldg(rowT + (size_t)xB[p] * CV + c);
        Ba[p] = __ldg(rowB + (size_t)xA[p] * CV + c);
        Bb[p] = __ldg(rowB + (size_t)xB[p] * CV + c);
    }

    #pragma unroll
    for (int px = 0; px < POOL; px++) {
        // prefetch px+2 into its slot (no deps on current compute)
        if (px + 2 < POOL) {
            const int s = (px + 2) % 3;
            Ta[s] = __ldg(rowT + (size_t)xA[px + 2] * CV + c);
            Tb[s] = __ldg(rowT + (size_t)xB[px + 2] * CV + c);
            Ba[s] = __ldg(rowB + (size_t)xA[px + 2] * CV + c);
            Bb[s] = __ldg(rowB + (size_t)xB[px + 2] * CV + c);
        }

        const int s = px % 3;
        const float4 ta = Ta[s], tb = Tb[s], ba = Ba[s], bb = Bb[s];

        const float wtx  = wx[px];
        const float wmtx = 1.0f - wtx;

        float4 res;
        res.x = (ta.x * wmtx + tb.x * wtx) * wmty + (ba.x * wmtx + bb.x * wtx) * wty;
        res.y = (ta.y * wmtx + tb.y * wtx) * wmty + (ba.y * wmtx + bb.y * wtx) * wty;
        res.z = (ta.z * wmtx + tb.z * wtx) * wmty + (ba.z * wmtx + bb.z * wtx) * wty;
        res.w = (ta.w * wmtx + tb.w * wtx) * wmty + (ba.w * wmtx + bb.w * wtx) * wty;

        o[px * CV] = res;
    }
}

extern "C" void kernel_launch(void* const* d_in, const int* in_sizes, int n_in,
                              void* d_out, int out_size)
{
    const float* img  = (const float*)d_in[0];
    const int*   rois = (const int*)d_in[1];
    float*       out  = (float*)d_out;

    dim3 grid(POOL, 1024);
    roi_pool_kernel<<<grid, 256>>>(img, rois, out);
}

// round 12
// speedup vs baseline: 1.0507x; 1.0507x over previous
#include <cuda_runtime.h>

// img:  (1, 64, 64, 1024) float32
// rois: (1, 1024, 4) int32  -> x, y, w, h
// out:  (1, 1024, 7, 7, 1024) float32
//
// One CTA per (roi, py); 256 threads, one float4 channel lane each.
// Block-uniform 3-way specialization to cut L1 wavefronts (the measured
// invariant bottleneck at ~70%):
//   path A: w<=2  -> only 2 unique columns; 4 loads (2 if ydup) vs 28
//   path B: y0==y1 -> top row only; 14 loads, no y-lerp
//   path C: general -> R6's proven batched 28-load loop
// All paths are straight-line with independent batched loads (no per-load
// predication, no select rotation).

#define POOL 7
#define HW 64
#define CV 256   // float4 lanes per pixel

__device__ __forceinline__ float4 lerp2d(float4 ta, float4 tb, float4 ba, float4 bb,
                                         float wmtx, float wtx, float wmty, float wty)
{
    float4 res;
    res.x = (ta.x * wmtx + tb.x * wtx) * wmty + (ba.x * wmtx + bb.x * wtx) * wty;
    res.y = (ta.y * wmtx + tb.y * wtx) * wmty + (ba.y * wmtx + bb.y * wtx) * wty;
    res.z = (ta.z * wmtx + tb.z * wtx) * wmty + (ba.z * wmtx + bb.z * wtx) * wty;
    res.w = (ta.w * wmtx + tb.w * wtx) * wmty + (ba.w * wmtx + bb.w * wtx) * wty;
    return res;
}

__device__ __forceinline__ float4 sel4(int p, float4 a, float4 b)
{
    float4 r;
    r.x = p ? a.x : b.x;
    r.y = p ? a.y : b.y;
    r.z = p ? a.z : b.z;
    r.w = p ? a.w : b.w;
    return r;
}

__global__ __launch_bounds__(256, 4) void roi_pool_kernel(
    const float* __restrict__ img_,
    const int* __restrict__ rois,
    float* __restrict__ out_)
{
    const float4* __restrict__ img = reinterpret_cast<const float4*>(img_);
    float4* __restrict__ out = reinterpret_cast<float4*>(out_);

    const int py  = blockIdx.x;   // 0..6
    const int roi = blockIdx.y;   // 0..1023

    const int4 r = reinterpret_cast<const int4*>(rois)[roi];
    const int rx = r.x, ry = r.y, rw = r.z, rh = r.w;

    // ---- y axis (once per block) ----
    const float sy   = (float)rh / (float)POOL;
    const float srcy = ((float)py + 0.5f) * sy - 0.5f;
    const float fy   = floorf(srcy);
    const float ty   = srcy - fy;
    const int ylo = min(max((int)fy,     0), rh - 1);
    const int yhi = min(max((int)fy + 1, 0), rh - 1);
    const int noty = (yhi != ylo);

    const float4* __restrict__ rowT = img + (size_t)((ry + ylo) * HW) * CV;
    const float4* __restrict__ rowB = img + (size_t)((ry + yhi) * HW) * CV;

    const int c = threadIdx.x;
    float4* __restrict__ o = out + ((size_t)roi * (POOL * POOL) + (size_t)py * POOL) * CV + c;

    const float sx   = (float)rw / (float)POOL;
    const float wty  = ty;
    const float wmty = 1.0f - ty;

    // ---- x coords / weights (block-uniform, precomputed) ----
    int xA[POOL], xB[POOL];
    float wx[POOL];
    #pragma unroll
    for (int px = 0; px < POOL; px++) {
        const float srcx = ((float)px + 0.5f) * sx - 0.5f;
        const float fx   = floorf(srcx);
        wx[px] = srcx - fx;
        const int xlo = min(max((int)fx,     0), rw - 1);
        const int xhi = min(max((int)fx + 1, 0), rw - 1);
        xA[px] = rx + xlo;
        xB[px] = rx + xhi;
    }

    if (rw <= 2) {
        // ---- path A: at most 2 unique columns: rx and rx+rw-1 ----
        const size_t q0 = (size_t)rx * CV + c;
        const size_t q1 = (size_t)(rx + rw - 1) * CV + c;
        const float4 t0 = __ldg(rowT + q0);
        const float4 t1 = __ldg(rowT + q1);
        float4 b0, b1;
        if (noty) {
            b0 = __ldg(rowB + q0);
            b1 = __ldg(rowB + q1);
        } else {
            b0 = t0;
            b1 = t1;
        }
        #pragma unroll
        for (int px = 0; px < POOL; px++) {
            const float wtx  = wx[px];
            const float wmtx = 1.0f - wtx;
            const int selA = (xA[px] != rx);
            const int selB = (xB[px] != rx);
            const float4 ta = sel4(selA, t1, t0);
            const float4 tb = sel4(selB, t1, t0);
            const float4 ba = sel4(selA, b1, b0);
            const float4 bb = sel4(selB, b1, b0);
            o[px * CV] = lerp2d(ta, tb, ba, bb, wmtx, wtx, wmty, wty);
        }
    } else if (!noty) {
        // ---- path B: bottom row == top row; x-lerp only ----
        #pragma unroll
        for (int px = 0; px < POOL; px++) {
            const float4 ta = __ldg(rowT + (size_t)xA[px] * CV + c);
            const float4 tb = __ldg(rowT + (size_t)xB[px] * CV + c);
            const float wtx  = wx[px];
            const float wmtx = 1.0f - wtx;
            float4 top;
            top.x = ta.x * wmtx + tb.x * wtx;
            top.y = ta.y * wmtx + tb.y * wtx;
            top.z = ta.z * wmtx + tb.z * wtx;
            top.w = ta.w * wmtx + tb.w * wtx;
            // reference computes top*(1-ty)+top*ty; fold (<=1 ulp, tol 1e-3)
            float4 res;
            res.x = top.x * wmty + top.x * wty;
            res.y = top.y * wmty + top.y * wty;
            res.z = top.z * wmty + top.z * wty;
            res.w = top.w * wmty + top.w * wty;
            o[px * CV] = res;
        }
    } else {
        // ---- path C: general (R6 proven loop) ----
        #pragma unroll
        for (int px = 0; px < POOL; px++) {
            const float4 ta = __ldg(rowT + (size_t)xA[px] * CV + c);
            const float4 tb = __ldg(rowT + (size_t)xB[px] * CV + c);
            const float4 ba = __ldg(rowB + (size_t)xA[px] * CV + c);
            const float4 bb = __ldg(rowB + (size_t)xB[px] * CV + c);
            const float wtx  = wx[px];
            const float wmtx = 1.0f - wtx;
            o[px * CV] = lerp2d(ta, tb, ba, bb, wmtx, wtx, wmty, wty);
        }
    }
}

extern "C" void kernel_launch(void* const* d_in, const int* in_sizes, int n_in,
                              void* d_out, int out_size)
{
    const float* img  = (const float*)d_in[0];
    const int*   rois = (const int*)d_in[1];
    float*       out  = (float*)d_out;

    dim3 grid(POOL, 1024);
    roi_pool_kernel<<<grid, 256>>>(img, rois, out);
}